// round 3
// baseline (speedup 1.0000x reference)
#include <cuda_runtime.h>
#include <math.h>

// Problem dims
#define BQ 8
#define TT 2048
#define EE 1024
#define HH 1024

// GEMM tile config
#define BM 128
#define BN 128
#define BK 16
#define LDAS 20     // BK + 4 pad (conflict-free fragment reads)
#define LDBS 136    // BN + 8 pad

// Scratch (allocation-free rule: __device__ globals)
__device__ float g_q[(long long)BQ * TT * HH];
__device__ float g_k[(long long)BQ * TT * HH];
__device__ float g_v[(long long)BQ * TT * HH];
__device__ float g_s[(long long)BQ * TT * TT];

__device__ __forceinline__ unsigned f2tf(float x) {
    unsigned r;
    asm("cvt.rna.tf32.f32 %0, %1;" : "=r"(r) : "f"(x));
    return r;
}

__device__ __forceinline__ void mma_tf32(float* c,
                                         unsigned a0, unsigned a1, unsigned a2, unsigned a3,
                                         unsigned b0, unsigned b1) {
    asm volatile(
        "mma.sync.aligned.m16n8k8.row.col.f32.tf32.tf32.f32 "
        "{%0,%1,%2,%3}, {%4,%5,%6,%7}, {%8,%9}, {%0,%1,%2,%3};"
        : "+f"(c[0]), "+f"(c[1]), "+f"(c[2]), "+f"(c[3])
        : "r"(a0), "r"(a1), "r"(a2), "r"(a3), "r"(b0), "r"(b1));
}

// ---------------------------------------------------------------------------
// C[M,N] = scale * A[M,K] * B[N,K]^T   (A, B row-major, K contiguous for both)
// Block computes C[m0:m0+128, n0:n0+128]. 256 threads, 8 warps (4m x 2n),
// warp tile 32x64 via m16n8k8 tf32 mma.
// CAUSAL: store only where global col <= global row (row/col local to batch).
// ---------------------------------------------------------------------------
template <bool CAUSAL>
__device__ __forceinline__ void gemm_nt(const float* __restrict__ A,
                                        const float* __restrict__ B,
                                        float* __restrict__ C,
                                        int lda, int ldb, int ldc,
                                        int K, int m0, int n0, float scale) {
    __shared__ unsigned As[BM * LDAS];
    __shared__ unsigned Bs[BN * LDAS];

    const int tid = threadIdx.x;
    const int warp = tid >> 5, lane = tid & 31;
    const int wm = warp >> 1;  // 0..3
    const int wn = warp & 1;   // 0..1

    float acc[2][8][4];
#pragma unroll
    for (int i = 0; i < 2; i++)
#pragma unroll
        for (int j = 0; j < 8; j++)
#pragma unroll
            for (int r = 0; r < 4; r++) acc[i][j][r] = 0.f;

    const int lr = tid >> 2;        // 0..63
    const int lc = (tid & 3) * 4;   // 0,4,8,12

    for (int kt = 0; kt < K; kt += BK) {
#pragma unroll
        for (int h = 0; h < 2; h++) {
            int row = lr + h * 64;
            float4 va = *reinterpret_cast<const float4*>(
                A + (size_t)(m0 + row) * lda + kt + lc);
            unsigned* da = &As[row * LDAS + lc];
            da[0] = f2tf(va.x); da[1] = f2tf(va.y);
            da[2] = f2tf(va.z); da[3] = f2tf(va.w);
            float4 vb = *reinterpret_cast<const float4*>(
                B + (size_t)(n0 + row) * ldb + kt + lc);
            unsigned* db = &Bs[row * LDAS + lc];
            db[0] = f2tf(vb.x); db[1] = f2tf(vb.y);
            db[2] = f2tf(vb.z); db[3] = f2tf(vb.w);
        }
        __syncthreads();

#pragma unroll
        for (int ks = 0; ks < BK; ks += 8) {
            unsigned a[2][4], b[8][2];
#pragma unroll
            for (int i = 0; i < 2; i++) {
                int r = wm * 32 + i * 16 + (lane >> 2);
                int c = ks + (lane & 3);
                a[i][0] = As[r * LDAS + c];
                a[i][1] = As[(r + 8) * LDAS + c];
                a[i][2] = As[r * LDAS + c + 4];
                a[i][3] = As[(r + 8) * LDAS + c + 4];
            }
#pragma unroll
            for (int j = 0; j < 8; j++) {
                int n = wn * 64 + j * 8 + (lane >> 2);
                int c = ks + (lane & 3);
                b[j][0] = Bs[n * LDAS + c];
                b[j][1] = Bs[n * LDAS + c + 4];
            }
#pragma unroll
            for (int i = 0; i < 2; i++)
#pragma unroll
                for (int j = 0; j < 8; j++)
                    mma_tf32(acc[i][j], a[i][0], a[i][1], a[i][2], a[i][3],
                             b[j][0], b[j][1]);
        }
        __syncthreads();
    }

#pragma unroll
    for (int i = 0; i < 2; i++) {
        int rbase = m0 + wm * 32 + i * 16 + (lane >> 2);
#pragma unroll
        for (int j = 0; j < 8; j++) {
            int cn = n0 + wn * 64 + j * 8 + (lane & 3) * 2;
#pragma unroll
            for (int h = 0; h < 2; h++) {
                int r = rbase + h * 8;
                float v0 = acc[i][j][2 * h + 0] * scale;
                float v1 = acc[i][j][2 * h + 1] * scale;
                if (!CAUSAL || cn <= r)     C[(size_t)r * ldc + cn]     = v0;
                if (!CAUSAL || cn + 1 <= r) C[(size_t)r * ldc + cn + 1] = v1;
            }
        }
    }
}

// ---------------------------------------------------------------------------
// C[M,N] = A[M,K] * B[K,N]   (A row-major K-contig, B row-major N-contig)
// ---------------------------------------------------------------------------
__device__ __forceinline__ void gemm_nn(const float* __restrict__ A,
                                        const float* __restrict__ B,
                                        float* __restrict__ C,
                                        int lda, int ldb, int ldc,
                                        int K, int m0, int n0) {
    __shared__ unsigned As[BM * LDAS];
    __shared__ unsigned Bs[BK * LDBS];

    const int tid = threadIdx.x;
    const int warp = tid >> 5, lane = tid & 31;
    const int wm = warp >> 1;
    const int wn = warp & 1;

    float acc[2][8][4];
#pragma unroll
    for (int i = 0; i < 2; i++)
#pragma unroll
        for (int j = 0; j < 8; j++)
#pragma unroll
            for (int r = 0; r < 4; r++) acc[i][j][r] = 0.f;

    const int lr = tid >> 2;
    const int lc = (tid & 3) * 4;
    const int br = tid >> 5;          // 0..7
    const int bc = (tid & 31) * 4;    // 0..124

    for (int kt = 0; kt < K; kt += BK) {
#pragma unroll
        for (int h = 0; h < 2; h++) {
            int row = lr + h * 64;
            float4 va = *reinterpret_cast<const float4*>(
                A + (size_t)(m0 + row) * lda + kt + lc);
            unsigned* da = &As[row * LDAS + lc];
            da[0] = f2tf(va.x); da[1] = f2tf(va.y);
            da[2] = f2tf(va.z); da[3] = f2tf(va.w);
            int krow = br + h * 8;    // 0..15
            float4 vb = *reinterpret_cast<const float4*>(
                B + (size_t)(kt + krow) * ldb + n0 + bc);
            unsigned* db = &Bs[krow * LDBS + bc];
            db[0] = f2tf(vb.x); db[1] = f2tf(vb.y);
            db[2] = f2tf(vb.z); db[3] = f2tf(vb.w);
        }
        __syncthreads();

#pragma unroll
        for (int ks = 0; ks < BK; ks += 8) {
            unsigned a[2][4], b[8][2];
#pragma unroll
            for (int i = 0; i < 2; i++) {
                int r = wm * 32 + i * 16 + (lane >> 2);
                int c = ks + (lane & 3);
                a[i][0] = As[r * LDAS + c];
                a[i][1] = As[(r + 8) * LDAS + c];
                a[i][2] = As[r * LDAS + c + 4];
                a[i][3] = As[(r + 8) * LDAS + c + 4];
            }
#pragma unroll
            for (int j = 0; j < 8; j++) {
                int n = wn * 64 + j * 8 + (lane >> 2);
                b[j][0] = Bs[(ks + (lane & 3)) * LDBS + n];
                b[j][1] = Bs[(ks + (lane & 3) + 4) * LDBS + n];
            }
#pragma unroll
            for (int i = 0; i < 2; i++)
#pragma unroll
                for (int j = 0; j < 8; j++)
                    mma_tf32(acc[i][j], a[i][0], a[i][1], a[i][2], a[i][3],
                             b[j][0], b[j][1]);
        }
        __syncthreads();
    }

#pragma unroll
    for (int i = 0; i < 2; i++) {
        int rbase = m0 + wm * 32 + i * 16 + (lane >> 2);
#pragma unroll
        for (int j = 0; j < 8; j++) {
            int cn = n0 + wn * 64 + j * 8 + (lane & 3) * 2;
#pragma unroll
            for (int h = 0; h < 2; h++) {
                int r = rbase + h * 8;
                C[(size_t)r * ldc + cn]     = acc[i][j][2 * h + 0];
                C[(size_t)r * ldc + cn + 1] = acc[i][j][2 * h + 1];
            }
        }
    }
}

// ---------------------------------------------------------------------------
// Kernels
// ---------------------------------------------------------------------------

// Q/K/V = x @ W^T ; grid (HH/BN, (BQ*TT)/BM, 3)
__global__ void __launch_bounds__(256) qkv_kernel(const float* __restrict__ x,
                                                  const float* __restrict__ Wk,
                                                  const float* __restrict__ Wq,
                                                  const float* __restrict__ Wv) {
    const float* W;
    float* out;
    switch (blockIdx.z) {
        case 0: W = Wq; out = g_q; break;
        case 1: W = Wk; out = g_k; break;
        default: W = Wv; out = g_v; break;
    }
    gemm_nt<false>(x, W, out, EE, EE, HH, EE,
                   blockIdx.y * BM, blockIdx.x * BN, 1.0f);
}

// S = (Q K^T) * E^-0.5, causal; grid (TT/BN, TT/BM, BQ)
__global__ void __launch_bounds__(256) score_kernel() {
    int b = blockIdx.z;
    int m0 = blockIdx.y * BM, n0 = blockIdx.x * BN;
    if (n0 > m0) return;  // tile entirely above the diagonal -> never read
    const float* Q = g_q + (size_t)b * TT * HH;
    const float* Kp = g_k + (size_t)b * TT * HH;
    float* S = g_s + (size_t)b * TT * TT;
    gemm_nt<true>(Q, Kp, S, HH, HH, TT, HH, m0, n0, 0.03125f);  // 1024^-0.5
}

// Row-wise causal softmax in place on g_s; zero-fills j > t. grid (BQ*TT)
__global__ void __launch_bounds__(256) softmax_kernel() {
    const int row = blockIdx.x;
    const int b = row >> 11;
    const int t = row & (TT - 1);
    float* S = g_s + (size_t)b * TT * TT + (size_t)t * TT;
    const int tid = threadIdx.x;
    const int lane = tid & 31, warp = tid >> 5;
    __shared__ float red[8];

    float v[8];
    float mx = -INFINITY;
#pragma unroll
    for (int i = 0; i < 8; i++) {
        int j = tid + i * 256;
        float s = (j <= t) ? S[j] : -INFINITY;
        v[i] = s;
        mx = fmaxf(mx, s);
    }
#pragma unroll
    for (int o = 16; o; o >>= 1) mx = fmaxf(mx, __shfl_xor_sync(0xffffffffu, mx, o));
    if (lane == 0) red[warp] = mx;
    __syncthreads();
    float bm = red[0];
#pragma unroll
    for (int w = 1; w < 8; w++) bm = fmaxf(bm, red[w]);
    __syncthreads();

    float sum = 0.f;
#pragma unroll
    for (int i = 0; i < 8; i++) {
        int j = tid + i * 256;
        float e = (j <= t) ? expf(v[i] - bm) : 0.f;
        v[i] = e;
        sum += e;
    }
#pragma unroll
    for (int o = 16; o; o >>= 1) sum += __shfl_xor_sync(0xffffffffu, sum, o);
    if (lane == 0) red[warp] = sum;
    __syncthreads();
    float tot = 0.f;
#pragma unroll
    for (int w = 0; w < 8; w++) tot += red[w];
    float inv = 1.f / tot;
#pragma unroll
    for (int i = 0; i < 8; i++) {
        int j = tid + i * 256;
        S[j] = v[i] * inv;
    }
}

// O = P V ; grid (HH/BN, TT/BM, BQ). P rows in this tile are zero for
// s > m0+127, so truncate the k-loop at m0+BM.
__global__ void __launch_bounds__(256) pv_kernel(float* __restrict__ out) {
    int b = blockIdx.z;
    int m0 = blockIdx.y * BM, n0 = blockIdx.x * BN;
    const float* P = g_s + (size_t)b * TT * TT;
    const float* V = g_v + (size_t)b * TT * HH;
    float* C = out + (size_t)b * TT * HH;
    gemm_nn(P, V, C, TT, HH, HH, m0 + BM, m0, n0);
}

// ---------------------------------------------------------------------------
extern "C" void kernel_launch(void* const* d_in, const int* in_sizes, int n_in,
                              void* d_out, int out_size) {
    const float* x  = (const float*)d_in[0];
    const float* Wk = (const float*)d_in[1];
    const float* Wq = (const float*)d_in[2];
    const float* Wv = (const float*)d_in[3];
    float* out = (float*)d_out;

    dim3 blk(256);
    qkv_kernel<<<dim3(HH / BN, (BQ * TT) / BM, 3), blk>>>(x, Wk, Wq, Wv);
    score_kernel<<<dim3(TT / BN, TT / BM, BQ), blk>>>();
    softmax_kernel<<<dim3(BQ * TT), blk>>>();
    pv_kernel<<<dim3(HH / BN, TT / BM, BQ), blk>>>(out);
}

// round 4
// speedup vs baseline: 1.0043x; 1.0043x over previous
#include <cuda_runtime.h>
#include <math.h>

// Problem dims
#define BQ 8
#define TT 2048
#define EE 1024
#define HH 1024

// GEMM tile config
#define BM 128
#define BN 128
#define BK 16
#define LDAS 20     // BK + 4 pad (conflict-free fragment reads)
#define LDBS 136    // BN + 8 pad

// Scratch (allocation-free rule: __device__ globals)
__device__ float g_q[(long long)BQ * TT * HH];
__device__ float g_k[(long long)BQ * TT * HH];
__device__ float g_v[(long long)BQ * TT * HH];
__device__ float g_s[(long long)BQ * TT * TT];

__device__ __forceinline__ unsigned f2tf(float x) {
    unsigned r;
    asm("cvt.rna.tf32.f32 %0, %1;" : "=r"(r) : "f"(x));
    return r;
}

__device__ __forceinline__ void mma_tf32(float* c,
                                         unsigned a0, unsigned a1, unsigned a2, unsigned a3,
                                         unsigned b0, unsigned b1) {
    asm volatile(
        "mma.sync.aligned.m16n8k8.row.col.f32.tf32.tf32.f32 "
        "{%0,%1,%2,%3}, {%4,%5,%6,%7}, {%8,%9}, {%0,%1,%2,%3};"
        : "+f"(c[0]), "+f"(c[1]), "+f"(c[2]), "+f"(c[3])
        : "r"(a0), "r"(a1), "r"(a2), "r"(a3), "r"(b0), "r"(b1));
}

// ---------------------------------------------------------------------------
// C[M,N] = scale * A[M,K] * B[N,K]^T   (A, B row-major, K contiguous for both)
// Block computes C[m0:m0+128, n0:n0+128]. 256 threads, 8 warps (4m x 2n),
// warp tile 32x64 via m16n8k8 tf32 mma.
// CAUSAL: store only where global col <= global row (row/col local to batch).
// ---------------------------------------------------------------------------
template <bool CAUSAL>
__device__ __forceinline__ void gemm_nt(const float* __restrict__ A,
                                        const float* __restrict__ B,
                                        float* __restrict__ C,
                                        int lda, int ldb, int ldc,
                                        int K, int m0, int n0, float scale) {
    __shared__ unsigned As[BM * LDAS];
    __shared__ unsigned Bs[BN * LDAS];

    const int tid = threadIdx.x;
    const int warp = tid >> 5, lane = tid & 31;
    const int wm = warp >> 1;  // 0..3
    const int wn = warp & 1;   // 0..1

    float acc[2][8][4];
#pragma unroll
    for (int i = 0; i < 2; i++)
#pragma unroll
        for (int j = 0; j < 8; j++)
#pragma unroll
            for (int r = 0; r < 4; r++) acc[i][j][r] = 0.f;

    const int lr = tid >> 2;        // 0..63
    const int lc = (tid & 3) * 4;   // 0,4,8,12

    for (int kt = 0; kt < K; kt += BK) {
#pragma unroll
        for (int h = 0; h < 2; h++) {
            int row = lr + h * 64;
            float4 va = *reinterpret_cast<const float4*>(
                A + (size_t)(m0 + row) * lda + kt + lc);
            unsigned* da = &As[row * LDAS + lc];
            da[0] = f2tf(va.x); da[1] = f2tf(va.y);
            da[2] = f2tf(va.z); da[3] = f2tf(va.w);
            float4 vb = *reinterpret_cast<const float4*>(
                B + (size_t)(n0 + row) * ldb + kt + lc);
            unsigned* db = &Bs[row * LDAS + lc];
            db[0] = f2tf(vb.x); db[1] = f2tf(vb.y);
            db[2] = f2tf(vb.z); db[3] = f2tf(vb.w);
        }
        __syncthreads();

#pragma unroll
        for (int ks = 0; ks < BK; ks += 8) {
            unsigned a[2][4], b[8][2];
#pragma unroll
            for (int i = 0; i < 2; i++) {
                int r = wm * 32 + i * 16 + (lane >> 2);
                int c = ks + (lane & 3);
                a[i][0] = As[r * LDAS + c];
                a[i][1] = As[(r + 8) * LDAS + c];
                a[i][2] = As[r * LDAS + c + 4];
                a[i][3] = As[(r + 8) * LDAS + c + 4];
            }
#pragma unroll
            for (int j = 0; j < 8; j++) {
                int n = wn * 64 + j * 8 + (lane >> 2);
                int c = ks + (lane & 3);
                b[j][0] = Bs[n * LDAS + c];
                b[j][1] = Bs[n * LDAS + c + 4];
            }
#pragma unroll
            for (int i = 0; i < 2; i++)
#pragma unroll
                for (int j = 0; j < 8; j++)
                    mma_tf32(acc[i][j], a[i][0], a[i][1], a[i][2], a[i][3],
                             b[j][0], b[j][1]);
        }
        __syncthreads();
    }

#pragma unroll
    for (int i = 0; i < 2; i++) {
        int rbase = m0 + wm * 32 + i * 16 + (lane >> 2);
#pragma unroll
        for (int j = 0; j < 8; j++) {
            int cn = n0 + wn * 64 + j * 8 + (lane & 3) * 2;
#pragma unroll
            for (int h = 0; h < 2; h++) {
                int r = rbase + h * 8;
                float v0 = acc[i][j][2 * h + 0] * scale;
                float v1 = acc[i][j][2 * h + 1] * scale;
                if (!CAUSAL || cn <= r)     C[(size_t)r * ldc + cn]     = v0;
                if (!CAUSAL || cn + 1 <= r) C[(size_t)r * ldc + cn + 1] = v1;
            }
        }
    }
}

// ---------------------------------------------------------------------------
// C[M,N] = A[M,K] * B[K,N]   (A row-major K-contig, B row-major N-contig)
// ---------------------------------------------------------------------------
__device__ __forceinline__ void gemm_nn(const float* __restrict__ A,
                                        const float* __restrict__ B,
                                        float* __restrict__ C,
                                        int lda, int ldb, int ldc,
                                        int K, int m0, int n0) {
    __shared__ unsigned As[BM * LDAS];
    __shared__ unsigned Bs[BK * LDBS];

    const int tid = threadIdx.x;
    const int warp = tid >> 5, lane = tid & 31;
    const int wm = warp >> 1;
    const int wn = warp & 1;

    float acc[2][8][4];
#pragma unroll
    for (int i = 0; i < 2; i++)
#pragma unroll
        for (int j = 0; j < 8; j++)
#pragma unroll
            for (int r = 0; r < 4; r++) acc[i][j][r] = 0.f;

    const int lr = tid >> 2;
    const int lc = (tid & 3) * 4;
    const int br = tid >> 5;          // 0..7
    const int bc = (tid & 31) * 4;    // 0..124

    for (int kt = 0; kt < K; kt += BK) {
#pragma unroll
        for (int h = 0; h < 2; h++) {
            int row = lr + h * 64;
            float4 va = *reinterpret_cast<const float4*>(
                A + (size_t)(m0 + row) * lda + kt + lc);
            unsigned* da = &As[row * LDAS + lc];
            da[0] = f2tf(va.x); da[1] = f2tf(va.y);
            da[2] = f2tf(va.z); da[3] = f2tf(va.w);
            int krow = br + h * 8;    // 0..15
            float4 vb = *reinterpret_cast<const float4*>(
                B + (size_t)(kt + krow) * ldb + n0 + bc);
            unsigned* db = &Bs[krow * LDBS + bc];
            db[0] = f2tf(vb.x); db[1] = f2tf(vb.y);
            db[2] = f2tf(vb.z); db[3] = f2tf(vb.w);
        }
        __syncthreads();

#pragma unroll
        for (int ks = 0; ks < BK; ks += 8) {
            unsigned a[2][4], b[8][2];
#pragma unroll
            for (int i = 0; i < 2; i++) {
                int r = wm * 32 + i * 16 + (lane >> 2);
                int c = ks + (lane & 3);
                a[i][0] = As[r * LDAS + c];
                a[i][1] = As[(r + 8) * LDAS + c];
                a[i][2] = As[r * LDAS + c + 4];
                a[i][3] = As[(r + 8) * LDAS + c + 4];
            }
#pragma unroll
            for (int j = 0; j < 8; j++) {
                int n = wn * 64 + j * 8 + (lane >> 2);
                b[j][0] = Bs[(ks + (lane & 3)) * LDBS + n];
                b[j][1] = Bs[(ks + (lane & 3) + 4) * LDBS + n];
            }
#pragma unroll
            for (int i = 0; i < 2; i++)
#pragma unroll
                for (int j = 0; j < 8; j++)
                    mma_tf32(acc[i][j], a[i][0], a[i][1], a[i][2], a[i][3],
                             b[j][0], b[j][1]);
        }
        __syncthreads();
    }

#pragma unroll
    for (int i = 0; i < 2; i++) {
        int rbase = m0 + wm * 32 + i * 16 + (lane >> 2);
#pragma unroll
        for (int j = 0; j < 8; j++) {
            int cn = n0 + wn * 64 + j * 8 + (lane & 3) * 2;
#pragma unroll
            for (int h = 0; h < 2; h++) {
                int r = rbase + h * 8;
                C[(size_t)r * ldc + cn]     = acc[i][j][2 * h + 0];
                C[(size_t)r * ldc + cn + 1] = acc[i][j][2 * h + 1];
            }
        }
    }
}

// ---------------------------------------------------------------------------
// Kernels
// ---------------------------------------------------------------------------

// Q/K/V = x @ W^T ; grid (HH/BN, (BQ*TT)/BM, 3)
__global__ void __launch_bounds__(256) qkv_kernel(const float* __restrict__ x,
                                                  const float* __restrict__ Wk,
                                                  const float* __restrict__ Wq,
                                                  const float* __restrict__ Wv) {
    const float* W;
    float* out;
    switch (blockIdx.z) {
        case 0: W = Wq; out = g_q; break;
        case 1: W = Wk; out = g_k; break;
        default: W = Wv; out = g_v; break;
    }
    gemm_nt<false>(x, W, out, EE, EE, HH, EE,
                   blockIdx.y * BM, blockIdx.x * BN, 1.0f);
}

// S = (Q K^T) * E^-0.5, causal; grid (TT/BN, TT/BM, BQ)
__global__ void __launch_bounds__(256) score_kernel() {
    int b = blockIdx.z;
    int m0 = blockIdx.y * BM, n0 = blockIdx.x * BN;
    if (n0 > m0) return;  // tile entirely above the diagonal -> never read
    const float* Q = g_q + (size_t)b * TT * HH;
    const float* Kp = g_k + (size_t)b * TT * HH;
    float* S = g_s + (size_t)b * TT * TT;
    gemm_nt<true>(Q, Kp, S, HH, HH, TT, HH, m0, n0, 0.03125f);  // 1024^-0.5
}

// Row-wise causal softmax in place on g_s; zero-fills j > t. grid (BQ*TT)
__global__ void __launch_bounds__(256) softmax_kernel() {
    const int row = blockIdx.x;
    const int b = row >> 11;
    const int t = row & (TT - 1);
    float* S = g_s + (size_t)b * TT * TT + (size_t)t * TT;
    const int tid = threadIdx.x;
    const int lane = tid & 31, warp = tid >> 5;
    __shared__ float red[8];

    float v[8];
    float mx = -INFINITY;
#pragma unroll
    for (int i = 0; i < 8; i++) {
        int j = tid + i * 256;
        float s = (j <= t) ? S[j] : -INFINITY;
        v[i] = s;
        mx = fmaxf(mx, s);
    }
#pragma unroll
    for (int o = 16; o; o >>= 1) mx = fmaxf(mx, __shfl_xor_sync(0xffffffffu, mx, o));
    if (lane == 0) red[warp] = mx;
    __syncthreads();
    float bm = red[0];
#pragma unroll
    for (int w = 1; w < 8; w++) bm = fmaxf(bm, red[w]);
    __syncthreads();

    float sum = 0.f;
#pragma unroll
    for (int i = 0; i < 8; i++) {
        int j = tid + i * 256;
        float e = (j <= t) ? expf(v[i] - bm) : 0.f;
        v[i] = e;
        sum += e;
    }
#pragma unroll
    for (int o = 16; o; o >>= 1) sum += __shfl_xor_sync(0xffffffffu, sum, o);
    if (lane == 0) red[warp] = sum;
    __syncthreads();
    float tot = 0.f;
#pragma unroll
    for (int w = 0; w < 8; w++) tot += red[w];
    float inv = 1.f / tot;
#pragma unroll
    for (int i = 0; i < 8; i++) {
        int j = tid + i * 256;
        S[j] = v[i] * inv;
    }
}

// O = P V ; grid (HH/BN, TT/BM, BQ). P rows in this tile are zero for
// s > m0+127, so truncate the k-loop at m0+BM.
__global__ void __launch_bounds__(256) pv_kernel(float* __restrict__ out) {
    int b = blockIdx.z;
    int m0 = blockIdx.y * BM, n0 = blockIdx.x * BN;
    const float* P = g_s + (size_t)b * TT * TT;
    const float* V = g_v + (size_t)b * TT * HH;
    float* C = out + (size_t)b * TT * HH;
    gemm_nn(P, V, C, TT, HH, HH, m0 + BM, m0, n0);
}

// ---------------------------------------------------------------------------
extern "C" void kernel_launch(void* const* d_in, const int* in_sizes, int n_in,
                              void* d_out, int out_size) {
    const float* x  = (const float*)d_in[0];
    const float* Wk = (const float*)d_in[1];
    const float* Wq = (const float*)d_in[2];
    const float* Wv = (const float*)d_in[3];
    float* out = (float*)d_out;

    dim3 blk(256);
    qkv_kernel<<<dim3(HH / BN, (BQ * TT) / BM, 3), blk>>>(x, Wk, Wq, Wv);
    score_kernel<<<dim3(TT / BN, TT / BM, BQ), blk>>>();
    softmax_kernel<<<dim3(BQ * TT), blk>>>();
    pv_kernel<<<dim3(HH / BN, TT / BM, BQ), blk>>>(out);
}

// round 5
// speedup vs baseline: 1.0062x; 1.0019x over previous
#include <cuda_runtime.h>
#include <math.h>

// Problem dims
#define BQ 8
#define TT 2048
#define EE 1024
#define HH 1024

// GEMM tile config
#define BM 128
#define BN 128
#define BK 16
#define LDAS 20     // BK + 4 pad (conflict-free fragment reads)
#define LDBS 136    // BN + 8 pad

// Scratch (allocation-free rule: __device__ globals)
__device__ float g_q[(long long)BQ * TT * HH];
__device__ float g_k[(long long)BQ * TT * HH];
__device__ float g_v[(long long)BQ * TT * HH];
__device__ float g_s[(long long)BQ * TT * TT];

__device__ __forceinline__ unsigned f2tf(float x) {
    unsigned r;
    asm("cvt.rna.tf32.f32 %0, %1;" : "=r"(r) : "f"(x));
    return r;
}

__device__ __forceinline__ void mma_tf32(float* c,
                                         unsigned a0, unsigned a1, unsigned a2, unsigned a3,
                                         unsigned b0, unsigned b1) {
    asm volatile(
        "mma.sync.aligned.m16n8k8.row.col.f32.tf32.tf32.f32 "
        "{%0,%1,%2,%3}, {%4,%5,%6,%7}, {%8,%9}, {%0,%1,%2,%3};"
        : "+f"(c[0]), "+f"(c[1]), "+f"(c[2]), "+f"(c[3])
        : "r"(a0), "r"(a1), "r"(a2), "r"(a3), "r"(b0), "r"(b1));
}

// ---------------------------------------------------------------------------
// C[M,N] = scale * A[M,K] * B[N,K]^T   (A, B row-major, K contiguous for both)
// Block computes C[m0:m0+128, n0:n0+128]. 256 threads, 8 warps (4m x 2n),
// warp tile 32x64 via m16n8k8 tf32 mma.
// CAUSAL: store only where global col <= global row (row/col local to batch).
// ---------------------------------------------------------------------------
template <bool CAUSAL>
__device__ __forceinline__ void gemm_nt(const float* __restrict__ A,
                                        const float* __restrict__ B,
                                        float* __restrict__ C,
                                        int lda, int ldb, int ldc,
                                        int K, int m0, int n0, float scale) {
    __shared__ unsigned As[BM * LDAS];
    __shared__ unsigned Bs[BN * LDAS];

    const int tid = threadIdx.x;
    const int warp = tid >> 5, lane = tid & 31;
    const int wm = warp >> 1;  // 0..3
    const int wn = warp & 1;   // 0..1

    float acc[2][8][4];
#pragma unroll
    for (int i = 0; i < 2; i++)
#pragma unroll
        for (int j = 0; j < 8; j++)
#pragma unroll
            for (int r = 0; r < 4; r++) acc[i][j][r] = 0.f;

    const int lr = tid >> 2;        // 0..63
    const int lc = (tid & 3) * 4;   // 0,4,8,12

    for (int kt = 0; kt < K; kt += BK) {
#pragma unroll
        for (int h = 0; h < 2; h++) {
            int row = lr + h * 64;
            float4 va = *reinterpret_cast<const float4*>(
                A + (size_t)(m0 + row) * lda + kt + lc);
            unsigned* da = &As[row * LDAS + lc];
            da[0] = f2tf(va.x); da[1] = f2tf(va.y);
            da[2] = f2tf(va.z); da[3] = f2tf(va.w);
            float4 vb = *reinterpret_cast<const float4*>(
                B + (size_t)(n0 + row) * ldb + kt + lc);
            unsigned* db = &Bs[row * LDAS + lc];
            db[0] = f2tf(vb.x); db[1] = f2tf(vb.y);
            db[2] = f2tf(vb.z); db[3] = f2tf(vb.w);
        }
        __syncthreads();

#pragma unroll
        for (int ks = 0; ks < BK; ks += 8) {
            unsigned a[2][4], b[8][2];
#pragma unroll
            for (int i = 0; i < 2; i++) {
                int r = wm * 32 + i * 16 + (lane >> 2);
                int c = ks + (lane & 3);
                a[i][0] = As[r * LDAS + c];
                a[i][1] = As[(r + 8) * LDAS + c];
                a[i][2] = As[r * LDAS + c + 4];
                a[i][3] = As[(r + 8) * LDAS + c + 4];
            }
#pragma unroll
            for (int j = 0; j < 8; j++) {
                int n = wn * 64 + j * 8 + (lane >> 2);
                int c = ks + (lane & 3);
                b[j][0] = Bs[n * LDAS + c];
                b[j][1] = Bs[n * LDAS + c + 4];
            }
#pragma unroll
            for (int i = 0; i < 2; i++)
#pragma unroll
                for (int j = 0; j < 8; j++)
                    mma_tf32(acc[i][j], a[i][0], a[i][1], a[i][2], a[i][3],
                             b[j][0], b[j][1]);
        }
        __syncthreads();
    }

#pragma unroll
    for (int i = 0; i < 2; i++) {
        int rbase = m0 + wm * 32 + i * 16 + (lane >> 2);
#pragma unroll
        for (int j = 0; j < 8; j++) {
            int cn = n0 + wn * 64 + j * 8 + (lane & 3) * 2;
#pragma unroll
            for (int h = 0; h < 2; h++) {
                int r = rbase + h * 8;
                float v0 = acc[i][j][2 * h + 0] * scale;
                float v1 = acc[i][j][2 * h + 1] * scale;
                if (!CAUSAL || cn <= r)     C[(size_t)r * ldc + cn]     = v0;
                if (!CAUSAL || cn + 1 <= r) C[(size_t)r * ldc + cn + 1] = v1;
            }
        }
    }
}

// ---------------------------------------------------------------------------
// C[M,N] = A[M,K] * B[K,N]   (A row-major K-contig, B row-major N-contig)
// ---------------------------------------------------------------------------
__device__ __forceinline__ void gemm_nn(const float* __restrict__ A,
                                        const float* __restrict__ B,
                                        float* __restrict__ C,
                                        int lda, int ldb, int ldc,
                                        int K, int m0, int n0) {
    __shared__ unsigned As[BM * LDAS];
    __shared__ unsigned Bs[BK * LDBS];

    const int tid = threadIdx.x;
    const int warp = tid >> 5, lane = tid & 31;
    const int wm = warp >> 1;
    const int wn = warp & 1;

    float acc[2][8][4];
#pragma unroll
    for (int i = 0; i < 2; i++)
#pragma unroll
        for (int j = 0; j < 8; j++)
#pragma unroll
            for (int r = 0; r < 4; r++) acc[i][j][r] = 0.f;

    const int lr = tid >> 2;
    const int lc = (tid & 3) * 4;
    const int br = tid >> 5;          // 0..7
    const int bc = (tid & 31) * 4;    // 0..124

    for (int kt = 0; kt < K; kt += BK) {
#pragma unroll
        for (int h = 0; h < 2; h++) {
            int row = lr + h * 64;
            float4 va = *reinterpret_cast<const float4*>(
                A + (size_t)(m0 + row) * lda + kt + lc);
            unsigned* da = &As[row * LDAS + lc];
            da[0] = f2tf(va.x); da[1] = f2tf(va.y);
            da[2] = f2tf(va.z); da[3] = f2tf(va.w);
            int krow = br + h * 8;    // 0..15
            float4 vb = *reinterpret_cast<const float4*>(
                B + (size_t)(kt + krow) * ldb + n0 + bc);
            unsigned* db = &Bs[krow * LDBS + bc];
            db[0] = f2tf(vb.x); db[1] = f2tf(vb.y);
            db[2] = f2tf(vb.z); db[3] = f2tf(vb.w);
        }
        __syncthreads();

#pragma unroll
        for (int ks = 0; ks < BK; ks += 8) {
            unsigned a[2][4], b[8][2];
#pragma unroll
            for (int i = 0; i < 2; i++) {
                int r = wm * 32 + i * 16 + (lane >> 2);
                int c = ks + (lane & 3);
                a[i][0] = As[r * LDAS + c];
                a[i][1] = As[(r + 8) * LDAS + c];
                a[i][2] = As[r * LDAS + c + 4];
                a[i][3] = As[(r + 8) * LDAS + c + 4];
            }
#pragma unroll
            for (int j = 0; j < 8; j++) {
                int n = wn * 64 + j * 8 + (lane >> 2);
                b[j][0] = Bs[(ks + (lane & 3)) * LDBS + n];
                b[j][1] = Bs[(ks + (lane & 3) + 4) * LDBS + n];
            }
#pragma unroll
            for (int i = 0; i < 2; i++)
#pragma unroll
                for (int j = 0; j < 8; j++)
                    mma_tf32(acc[i][j], a[i][0], a[i][1], a[i][2], a[i][3],
                             b[j][0], b[j][1]);
        }
        __syncthreads();
    }

#pragma unroll
    for (int i = 0; i < 2; i++) {
        int rbase = m0 + wm * 32 + i * 16 + (lane >> 2);
#pragma unroll
        for (int j = 0; j < 8; j++) {
            int cn = n0 + wn * 64 + j * 8 + (lane & 3) * 2;
#pragma unroll
            for (int h = 0; h < 2; h++) {
                int r = rbase + h * 8;
                C[(size_t)r * ldc + cn]     = acc[i][j][2 * h + 0];
                C[(size_t)r * ldc + cn + 1] = acc[i][j][2 * h + 1];
            }
        }
    }
}

// ---------------------------------------------------------------------------
// Kernels
// ---------------------------------------------------------------------------

// Q/K/V = x @ W^T ; grid (HH/BN, (BQ*TT)/BM, 3)
__global__ void __launch_bounds__(256) qkv_kernel(const float* __restrict__ x,
                                                  const float* __restrict__ Wk,
                                                  const float* __restrict__ Wq,
                                                  const float* __restrict__ Wv) {
    const float* W;
    float* out;
    switch (blockIdx.z) {
        case 0: W = Wq; out = g_q; break;
        case 1: W = Wk; out = g_k; break;
        default: W = Wv; out = g_v; break;
    }
    gemm_nt<false>(x, W, out, EE, EE, HH, EE,
                   blockIdx.y * BM, blockIdx.x * BN, 1.0f);
}

// S = (Q K^T) * E^-0.5, causal; grid (TT/BN, TT/BM, BQ)
__global__ void __launch_bounds__(256) score_kernel() {
    int b = blockIdx.z;
    int m0 = blockIdx.y * BM, n0 = blockIdx.x * BN;
    if (n0 > m0) return;  // tile entirely above the diagonal -> never read
    const float* Q = g_q + (size_t)b * TT * HH;
    const float* Kp = g_k + (size_t)b * TT * HH;
    float* S = g_s + (size_t)b * TT * TT;
    gemm_nt<true>(Q, Kp, S, HH, HH, TT, HH, m0, n0, 0.03125f);  // 1024^-0.5
}

// Row-wise causal softmax in place on g_s; zero-fills j > t. grid (BQ*TT)
__global__ void __launch_bounds__(256) softmax_kernel() {
    const int row = blockIdx.x;
    const int b = row >> 11;
    const int t = row & (TT - 1);
    float* S = g_s + (size_t)b * TT * TT + (size_t)t * TT;
    const int tid = threadIdx.x;
    const int lane = tid & 31, warp = tid >> 5;
    __shared__ float red[8];

    float v[8];
    float mx = -INFINITY;
#pragma unroll
    for (int i = 0; i < 8; i++) {
        int j = tid + i * 256;
        float s = (j <= t) ? S[j] : -INFINITY;
        v[i] = s;
        mx = fmaxf(mx, s);
    }
#pragma unroll
    for (int o = 16; o; o >>= 1) mx = fmaxf(mx, __shfl_xor_sync(0xffffffffu, mx, o));
    if (lane == 0) red[warp] = mx;
    __syncthreads();
    float bm = red[0];
#pragma unroll
    for (int w = 1; w < 8; w++) bm = fmaxf(bm, red[w]);
    __syncthreads();

    float sum = 0.f;
#pragma unroll
    for (int i = 0; i < 8; i++) {
        int j = tid + i * 256;
        float e = (j <= t) ? expf(v[i] - bm) : 0.f;
        v[i] = e;
        sum += e;
    }
#pragma unroll
    for (int o = 16; o; o >>= 1) sum += __shfl_xor_sync(0xffffffffu, sum, o);
    if (lane == 0) red[warp] = sum;
    __syncthreads();
    float tot = 0.f;
#pragma unroll
    for (int w = 0; w < 8; w++) tot += red[w];
    float inv = 1.f / tot;
#pragma unroll
    for (int i = 0; i < 8; i++) {
        int j = tid + i * 256;
        S[j] = v[i] * inv;
    }
}

// O = P V ; grid (HH/BN, TT/BM, BQ). P rows in this tile are zero for
// s > m0+127, so truncate the k-loop at m0+BM.
__global__ void __launch_bounds__(256) pv_kernel(float* __restrict__ out) {
    int b = blockIdx.z;
    int m0 = blockIdx.y * BM, n0 = blockIdx.x * BN;
    const float* P = g_s + (size_t)b * TT * TT;
    const float* V = g_v + (size_t)b * TT * HH;
    float* C = out + (size_t)b * TT * HH;
    gemm_nn(P, V, C, TT, HH, HH, m0 + BM, m0, n0);
}

// ---------------------------------------------------------------------------
extern "C" void kernel_launch(void* const* d_in, const int* in_sizes, int n_in,
                              void* d_out, int out_size) {
    const float* x  = (const float*)d_in[0];
    const float* Wk = (const float*)d_in[1];
    const float* Wq = (const float*)d_in[2];
    const float* Wv = (const float*)d_in[3];
    float* out = (float*)d_out;

    dim3 blk(256);
    qkv_kernel<<<dim3(HH / BN, (BQ * TT) / BM, 3), blk>>>(x, Wk, Wq, Wv);
    score_kernel<<<dim3(TT / BN, TT / BM, BQ), blk>>>();
    softmax_kernel<<<dim3(BQ * TT), blk>>>();
    pv_kernel<<<dim3(HH / BN, TT / BM, BQ), blk>>>(out);
}

// round 6
// speedup vs baseline: 1.1683x; 1.1611x over previous
#include <cuda_runtime.h>
#include <math.h>

// Problem dims
#define BQ 8
#define TT 2048
#define EE 1024
#define HH 1024

// GEMM tile config
#define BM 128
#define BN 128
#define BK 16
#define LDAS 20     // BK + 4 pad (conflict-free fragment reads)
#define LDBS 136    // BN + 8 pad

// Scratch (allocation-free rule: __device__ globals)
__device__ float g_q[(long long)BQ * TT * HH];
__device__ float g_k[(long long)BQ * TT * HH];
__device__ float g_v[(long long)BQ * TT * HH];
__device__ float g_s[(long long)BQ * TT * TT];

__device__ __forceinline__ unsigned f2tf(float x) {
    unsigned r;
    asm("cvt.rna.tf32.f32 %0, %1;" : "=r"(r) : "f"(x));
    return r;
}

__device__ __forceinline__ void mma_tf32(float* c,
                                         unsigned a0, unsigned a1, unsigned a2, unsigned a3,
                                         unsigned b0, unsigned b1) {
    asm volatile(
        "mma.sync.aligned.m16n8k8.row.col.f32.tf32.tf32.f32 "
        "{%0,%1,%2,%3}, {%4,%5,%6,%7}, {%8,%9}, {%0,%1,%2,%3};"
        : "+f"(c[0]), "+f"(c[1]), "+f"(c[2]), "+f"(c[3])
        : "r"(a0), "r"(a1), "r"(a2), "r"(a3), "r"(b0), "r"(b1));
}

__device__ __forceinline__ unsigned smem_u32(const void* p) {
    return (unsigned)__cvta_generic_to_shared(p);
}
__device__ __forceinline__ void cp_async16(unsigned dst, const void* src) {
    asm volatile("cp.async.cg.shared.global [%0], [%1], 16;" :: "r"(dst), "l"(src));
}
__device__ __forceinline__ void cp_commit() {
    asm volatile("cp.async.commit_group;");
}
__device__ __forceinline__ void cp_wait1() {
    asm volatile("cp.async.wait_group 1;");
}

// ---------------------------------------------------------------------------
// C[M,N] = scale * A[M,K] * B[N,K]^T   (A, B row-major, K contiguous for both)
// 256 threads, 8 warps (4m x 2n), warp tile 32x64, m16n8k8 tf32 mma.
// cp.async double-buffered mainloop; cvt to tf32 at fragment load.
// CAUSAL: store only where global col <= global row.
// ---------------------------------------------------------------------------
template <bool CAUSAL>
__device__ __forceinline__ void gemm_nt(const float* __restrict__ A,
                                        const float* __restrict__ B,
                                        float* __restrict__ C,
                                        int lda, int ldb, int ldc,
                                        int K, int m0, int n0, float scale) {
    __shared__ float As[2][BM * LDAS];
    __shared__ float Bs[2][BM * LDAS];

    const int tid = threadIdx.x;
    const int warp = tid >> 5, lane = tid & 31;
    const int wm = warp >> 1;  // 0..3
    const int wn = warp & 1;   // 0..1

    float acc[2][8][4];
#pragma unroll
    for (int i = 0; i < 2; i++)
#pragma unroll
        for (int j = 0; j < 8; j++)
#pragma unroll
            for (int r = 0; r < 4; r++) acc[i][j][r] = 0.f;

    const int lr = tid >> 2;        // 0..63
    const int lc4 = (tid & 3) * 4;  // 0,4,8,12
    const float* Ag = A + (size_t)(m0 + lr) * lda + lc4;
    const float* Bg = B + (size_t)(n0 + lr) * ldb + lc4;

    auto issue = [&](int s, int kt) {
#pragma unroll
        for (int h = 0; h < 2; h++) {
            cp_async16(smem_u32(&As[s][(lr + 64 * h) * LDAS + lc4]),
                       Ag + (size_t)(64 * h) * lda + kt);
            cp_async16(smem_u32(&Bs[s][(lr + 64 * h) * LDAS + lc4]),
                       Bg + (size_t)(64 * h) * ldb + kt);
        }
    };

    const int nk = K / BK;
    issue(0, 0);
    cp_commit();

    for (int kt = 0; kt < nk; kt++) {
        if (kt + 1 < nk) issue((kt + 1) & 1, (kt + 1) * BK);
        cp_commit();
        cp_wait1();
        __syncthreads();
        const float* as = As[kt & 1];
        const float* bs = Bs[kt & 1];

#pragma unroll
        for (int ks = 0; ks < BK; ks += 8) {
            unsigned a[2][4], b[8][2];
#pragma unroll
            for (int i = 0; i < 2; i++) {
                int r = wm * 32 + i * 16 + (lane >> 2);
                int c = ks + (lane & 3);
                a[i][0] = f2tf(as[r * LDAS + c]);
                a[i][1] = f2tf(as[(r + 8) * LDAS + c]);
                a[i][2] = f2tf(as[r * LDAS + c + 4]);
                a[i][3] = f2tf(as[(r + 8) * LDAS + c + 4]);
            }
#pragma unroll
            for (int j = 0; j < 8; j++) {
                int n = wn * 64 + j * 8 + (lane >> 2);
                int c = ks + (lane & 3);
                b[j][0] = f2tf(bs[n * LDAS + c]);
                b[j][1] = f2tf(bs[n * LDAS + c + 4]);
            }
#pragma unroll
            for (int i = 0; i < 2; i++)
#pragma unroll
                for (int j = 0; j < 8; j++)
                    mma_tf32(acc[i][j], a[i][0], a[i][1], a[i][2], a[i][3],
                             b[j][0], b[j][1]);
        }
        __syncthreads();
    }

#pragma unroll
    for (int i = 0; i < 2; i++) {
        int rbase = m0 + wm * 32 + i * 16 + (lane >> 2);
#pragma unroll
        for (int j = 0; j < 8; j++) {
            int cn = n0 + wn * 64 + j * 8 + (lane & 3) * 2;
#pragma unroll
            for (int h = 0; h < 2; h++) {
                int r = rbase + h * 8;
                float v0 = acc[i][j][2 * h + 0] * scale;
                float v1 = acc[i][j][2 * h + 1] * scale;
                if (CAUSAL) {
                    if (cn <= r)     C[(size_t)r * ldc + cn]     = v0;
                    if (cn + 1 <= r) C[(size_t)r * ldc + cn + 1] = v1;
                } else {
                    *reinterpret_cast<float2*>(C + (size_t)r * ldc + cn) =
                        make_float2(v0, v1);
                }
            }
        }
    }
}

// ---------------------------------------------------------------------------
// C[M,N] = A[M,K] * B[K,N]   (A row-major K-contig, B row-major N-contig)
// ---------------------------------------------------------------------------
__device__ __forceinline__ void gemm_nn(const float* __restrict__ A,
                                        const float* __restrict__ B,
                                        float* __restrict__ C,
                                        int lda, int ldb, int ldc,
                                        int K, int m0, int n0) {
    __shared__ float As[2][BM * LDAS];
    __shared__ float Bs[2][BK * LDBS];

    const int tid = threadIdx.x;
    const int warp = tid >> 5, lane = tid & 31;
    const int wm = warp >> 1;
    const int wn = warp & 1;

    float acc[2][8][4];
#pragma unroll
    for (int i = 0; i < 2; i++)
#pragma unroll
        for (int j = 0; j < 8; j++)
#pragma unroll
            for (int r = 0; r < 4; r++) acc[i][j][r] = 0.f;

    const int lr = tid >> 2;          // 0..63
    const int lc4 = (tid & 3) * 4;    // 0,4,8,12
    const int br = tid >> 5;          // 0..7
    const int bc = (tid & 31) * 4;    // 0..124
    const float* Ag = A + (size_t)(m0 + lr) * lda + lc4;
    const float* Bg = B + n0 + bc;

    auto issue = [&](int s, int kt) {
#pragma unroll
        for (int h = 0; h < 2; h++) {
            cp_async16(smem_u32(&As[s][(lr + 64 * h) * LDAS + lc4]),
                       Ag + (size_t)(64 * h) * lda + kt);
            int krow = br + h * 8;  // 0..15
            cp_async16(smem_u32(&Bs[s][krow * LDBS + bc]),
                       Bg + (size_t)(kt + krow) * ldb);
        }
    };

    const int nk = K / BK;
    issue(0, 0);
    cp_commit();

    for (int kt = 0; kt < nk; kt++) {
        if (kt + 1 < nk) issue((kt + 1) & 1, (kt + 1) * BK);
        cp_commit();
        cp_wait1();
        __syncthreads();
        const float* as = As[kt & 1];
        const float* bs = Bs[kt & 1];

#pragma unroll
        for (int ks = 0; ks < BK; ks += 8) {
            unsigned a[2][4], b[8][2];
#pragma unroll
            for (int i = 0; i < 2; i++) {
                int r = wm * 32 + i * 16 + (lane >> 2);
                int c = ks + (lane & 3);
                a[i][0] = f2tf(as[r * LDAS + c]);
                a[i][1] = f2tf(as[(r + 8) * LDAS + c]);
                a[i][2] = f2tf(as[r * LDAS + c + 4]);
                a[i][3] = f2tf(as[(r + 8) * LDAS + c + 4]);
            }
#pragma unroll
            for (int j = 0; j < 8; j++) {
                int n = wn * 64 + j * 8 + (lane >> 2);
                b[j][0] = f2tf(bs[(ks + (lane & 3)) * LDBS + n]);
                b[j][1] = f2tf(bs[(ks + (lane & 3) + 4) * LDBS + n]);
            }
#pragma unroll
            for (int i = 0; i < 2; i++)
#pragma unroll
                for (int j = 0; j < 8; j++)
                    mma_tf32(acc[i][j], a[i][0], a[i][1], a[i][2], a[i][3],
                             b[j][0], b[j][1]);
        }
        __syncthreads();
    }

#pragma unroll
    for (int i = 0; i < 2; i++) {
        int rbase = m0 + wm * 32 + i * 16 + (lane >> 2);
#pragma unroll
        for (int j = 0; j < 8; j++) {
            int cn = n0 + wn * 64 + j * 8 + (lane & 3) * 2;
#pragma unroll
            for (int h = 0; h < 2; h++) {
                int r = rbase + h * 8;
                *reinterpret_cast<float2*>(C + (size_t)r * ldc + cn) =
                    make_float2(acc[i][j][2 * h + 0], acc[i][j][2 * h + 1]);
            }
        }
    }
}

// ---------------------------------------------------------------------------
// Kernels
// ---------------------------------------------------------------------------

// Q/K/V = x @ W^T ; grid (HH/BN, (BQ*TT)/BM, 3)
__global__ void __launch_bounds__(256) qkv_kernel(const float* __restrict__ x,
                                                  const float* __restrict__ Wk,
                                                  const float* __restrict__ Wq,
                                                  const float* __restrict__ Wv) {
    const float* W;
    float* out;
    switch (blockIdx.z) {
        case 0: W = Wq; out = g_q; break;
        case 1: W = Wk; out = g_k; break;
        default: W = Wv; out = g_v; break;
    }
    gemm_nt<false>(x, W, out, EE, EE, HH, EE,
                   blockIdx.y * BM, blockIdx.x * BN, 1.0f);
}

// S = (Q K^T) * E^-0.5, causal; grid (TT/BN, TT/BM, BQ)
__global__ void __launch_bounds__(256) score_kernel() {
    int b = blockIdx.z;
    int m0 = blockIdx.y * BM, n0 = blockIdx.x * BN;
    if (n0 > m0) return;  // tile entirely above the diagonal -> never read
    const float* Q = g_q + (size_t)b * TT * HH;
    const float* Kp = g_k + (size_t)b * TT * HH;
    float* S = g_s + (size_t)b * TT * TT;
    gemm_nt<true>(Q, Kp, S, HH, HH, TT, HH, m0, n0, 0.03125f);  // 1024^-0.5
}

// Row-wise causal softmax in place on g_s. Zero-fills only up to the
// 128-rounded row boundary (all pv_kernel ever reads). grid (BQ*TT)
__global__ void __launch_bounds__(256) softmax_kernel() {
    const int row = blockIdx.x;
    const int b = row >> 11;
    const int t = row & (TT - 1);
    float* S = g_s + (size_t)b * TT * TT + (size_t)t * TT;
    const int tid = threadIdx.x;
    const int lane = tid & 31, warp = tid >> 5;
    const int limit = (t & ~127) + 128;  // pv reads cols [0, limit)
    __shared__ float red[8];

    float v[8];
    float mx = -INFINITY;
#pragma unroll
    for (int i = 0; i < 8; i++) {
        int j = tid + i * 256;
        float s = (j <= t) ? S[j] : -INFINITY;
        v[i] = s;
        mx = fmaxf(mx, s);
    }
#pragma unroll
    for (int o = 16; o; o >>= 1) mx = fmaxf(mx, __shfl_xor_sync(0xffffffffu, mx, o));
    if (lane == 0) red[warp] = mx;
    __syncthreads();
    float bm = red[0];
#pragma unroll
    for (int w = 1; w < 8; w++) bm = fmaxf(bm, red[w]);
    __syncthreads();

    float sum = 0.f;
#pragma unroll
    for (int i = 0; i < 8; i++) {
        int j = tid + i * 256;
        float e = (j <= t) ? expf(v[i] - bm) : 0.f;
        v[i] = e;
        sum += e;
    }
#pragma unroll
    for (int o = 16; o; o >>= 1) sum += __shfl_xor_sync(0xffffffffu, sum, o);
    if (lane == 0) red[warp] = sum;
    __syncthreads();
    float tot = 0.f;
#pragma unroll
    for (int w = 0; w < 8; w++) tot += red[w];
    float inv = 1.f / tot;
#pragma unroll
    for (int i = 0; i < 8; i++) {
        int j = tid + i * 256;
        if (j < limit) S[j] = v[i] * inv;
    }
}

// O = P V ; grid (HH/BN, TT/BM, BQ). P rows in this tile are zero for
// s >= m0+128, so truncate the k-loop at m0+BM.
__global__ void __launch_bounds__(256) pv_kernel(float* __restrict__ out) {
    int b = blockIdx.z;
    int m0 = blockIdx.y * BM, n0 = blockIdx.x * BN;
    const float* P = g_s + (size_t)b * TT * TT;
    const float* V = g_v + (size_t)b * TT * HH;
    float* C = out + (size_t)b * TT * HH;
    gemm_nn(P, V, C, TT, HH, HH, m0 + BM, m0, n0);
}

// ---------------------------------------------------------------------------
extern "C" void kernel_launch(void* const* d_in, const int* in_sizes, int n_in,
                              void* d_out, int out_size) {
    const float* x  = (const float*)d_in[0];
    const float* Wk = (const float*)d_in[1];
    const float* Wq = (const float*)d_in[2];
    const float* Wv = (const float*)d_in[3];
    float* out = (float*)d_out;

    dim3 blk(256);
    qkv_kernel<<<dim3(HH / BN, (BQ * TT) / BM, 3), blk>>>(x, Wk, Wq, Wv);
    score_kernel<<<dim3(TT / BN, TT / BM, BQ), blk>>>();
    softmax_kernel<<<dim3(BQ * TT), blk>>>();
    pv_kernel<<<dim3(HH / BN, TT / BM, BQ), blk>>>(out);
}

// round 8
// speedup vs baseline: 1.1779x; 1.0082x over previous
#include <cuda_runtime.h>
#include <math.h>

// Problem dims
#define BQ 8
#define TT 2048
#define EE 1024
#define HH 1024

// GEMM tile config
#define BM 128
#define BN 128
#define BK 16
#define LDAS 20     // BK + 4 pad -> conflict-free fragment reads

// Scratch (allocation-free rule: __device__ globals).
// NOTE: these symbols must ONLY be referenced from device code. Taking their
// address in host code yields the host shadow symbol (silently "works" on
// GB300 via ATS and corrupts nothing visible) — that was the R7 bug.
__device__ float g_x [(long long)BQ * TT * EE];   // tf32-rounded x
__device__ float g_wq[(long long)HH * EE];        // tf32-rounded weights
__device__ float g_wk[(long long)HH * EE];
__device__ float g_wv[(long long)HH * EE];
__device__ float g_q [(long long)BQ * TT * HH];   // rounded at store
__device__ float g_k [(long long)BQ * TT * HH];
__device__ float g_v [(long long)BQ * TT * HH];
__device__ float g_vt[(long long)BQ * HH * TT];   // V transposed [b][h][s]
__device__ float g_s [(long long)BQ * TT * TT];   // scores / probs

__device__ __forceinline__ unsigned f2tf(float x) {
    unsigned r;
    asm("cvt.rna.tf32.f32 %0, %1;" : "=r"(r) : "f"(x));
    return r;
}
__device__ __forceinline__ float roundtf(float x) {
    return __uint_as_float(f2tf(x));
}

__device__ __forceinline__ void mma_tf32(float* c,
                                         unsigned a0, unsigned a1, unsigned a2, unsigned a3,
                                         unsigned b0, unsigned b1) {
    asm volatile(
        "mma.sync.aligned.m16n8k8.row.col.f32.tf32.tf32.f32 "
        "{%0,%1,%2,%3}, {%4,%5,%6,%7}, {%8,%9}, {%0,%1,%2,%3};"
        : "+f"(c[0]), "+f"(c[1]), "+f"(c[2]), "+f"(c[3])
        : "r"(a0), "r"(a1), "r"(a2), "r"(a3), "r"(b0), "r"(b1));
}

__device__ __forceinline__ unsigned smem_u32(const void* p) {
    return (unsigned)__cvta_generic_to_shared(p);
}
__device__ __forceinline__ void cp_async16(unsigned dst, const void* src) {
    asm volatile("cp.async.cg.shared.global [%0], [%1], 16;" :: "r"(dst), "l"(src));
}
__device__ __forceinline__ void cp_commit() {
    asm volatile("cp.async.commit_group;");
}
__device__ __forceinline__ void cp_wait0() {
    asm volatile("cp.async.wait_group 0;");
}

// ---------------------------------------------------------------------------
// C[M,N] = scale * A[M,K] * B[N,K]^T  (A,B row-major, K contiguous for both).
// Inputs must be PRE-ROUNDED to tf32 (bits passed straight to mma).
// 256 threads, 8 warps (4m x 2n), warp tile 32x64, m16n8k8 tf32 mma.
// Double-buffered cp.async, ONE barrier per k-tile (issue strictly after the
// barrier, so the barrier protects both data-ready and buffer-reuse).
// CAUSAL: store only where global col <= global row.
// ROUND:  store outputs rounded to tf32.
// ---------------------------------------------------------------------------
template <bool CAUSAL, bool ROUND>
__device__ __forceinline__ void gemm_nt(const float* __restrict__ A,
                                        const float* __restrict__ B,
                                        float* __restrict__ C,
                                        int lda, int ldb, int ldc,
                                        int K, int m0, int n0, float scale) {
    __shared__ unsigned As[2][BM * LDAS];
    __shared__ unsigned Bs[2][BM * LDAS];

    const int tid = threadIdx.x;
    const int warp = tid >> 5, lane = tid & 31;
    const int wm = warp >> 1;  // 0..3
    const int wn = warp & 1;   // 0..1

    float acc[2][8][4];
#pragma unroll
    for (int i = 0; i < 2; i++)
#pragma unroll
        for (int j = 0; j < 8; j++)
#pragma unroll
            for (int r = 0; r < 4; r++) acc[i][j][r] = 0.f;

    const int lr = tid >> 2;        // 0..63
    const int lc4 = (tid & 3) * 4;  // 0,4,8,12
    const float* Ag = A + (size_t)(m0 + lr) * lda + lc4;
    const float* Bg = B + (size_t)(n0 + lr) * ldb + lc4;

    auto issue = [&](int s, int kt) {
#pragma unroll
        for (int h = 0; h < 2; h++) {
            cp_async16(smem_u32(&As[s][(lr + 64 * h) * LDAS + lc4]),
                       Ag + (size_t)(64 * h) * lda + kt);
            cp_async16(smem_u32(&Bs[s][(lr + 64 * h) * LDAS + lc4]),
                       Bg + (size_t)(64 * h) * ldb + kt);
        }
        cp_commit();
    };

    const int nk = K / BK;
    issue(0, 0);

    for (int kt = 0; kt < nk; kt++) {
        cp_wait0();
        __syncthreads();
        if (kt + 1 < nk) issue((kt + 1) & 1, (kt + 1) * BK);

        const unsigned* as = As[kt & 1];
        const unsigned* bs = Bs[kt & 1];

#pragma unroll
        for (int ks = 0; ks < BK; ks += 8) {
            unsigned a[2][4], b[8][2];
#pragma unroll
            for (int i = 0; i < 2; i++) {
                int r = wm * 32 + i * 16 + (lane >> 2);
                int c = ks + (lane & 3);
                a[i][0] = as[r * LDAS + c];
                a[i][1] = as[(r + 8) * LDAS + c];
                a[i][2] = as[r * LDAS + c + 4];
                a[i][3] = as[(r + 8) * LDAS + c + 4];
            }
#pragma unroll
            for (int j = 0; j < 8; j++) {
                int n = wn * 64 + j * 8 + (lane >> 2);
                int c = ks + (lane & 3);
                b[j][0] = bs[n * LDAS + c];
                b[j][1] = bs[n * LDAS + c + 4];
            }
#pragma unroll
            for (int i = 0; i < 2; i++)
#pragma unroll
                for (int j = 0; j < 8; j++)
                    mma_tf32(acc[i][j], a[i][0], a[i][1], a[i][2], a[i][3],
                             b[j][0], b[j][1]);
        }
    }

#pragma unroll
    for (int i = 0; i < 2; i++) {
        int rbase = m0 + wm * 32 + i * 16 + (lane >> 2);
#pragma unroll
        for (int j = 0; j < 8; j++) {
            int cn = n0 + wn * 64 + j * 8 + (lane & 3) * 2;
#pragma unroll
            for (int h = 0; h < 2; h++) {
                int r = rbase + h * 8;
                float v0 = acc[i][j][2 * h + 0] * scale;
                float v1 = acc[i][j][2 * h + 1] * scale;
                if (ROUND) { v0 = roundtf(v0); v1 = roundtf(v1); }
                if (CAUSAL) {
                    if (cn <= r)     C[(size_t)r * ldc + cn]     = v0;
                    if (cn + 1 <= r) C[(size_t)r * ldc + cn + 1] = v1;
                } else {
                    *reinterpret_cast<float2*>(C + (size_t)r * ldc + cn) =
                        make_float2(v0, v1);
                }
            }
        }
    }
}

// ---------------------------------------------------------------------------
// Kernels
// ---------------------------------------------------------------------------

// Elementwise tf32 pre-round into a device-global scratch selected DEVICE-SIDE
// (host code must never take a __device__ symbol's address).
__global__ void __launch_bounds__(256) round_kernel(const float4* __restrict__ src,
                                                    int which) {
    float4* dst;
    switch (which) {
        case 0:  dst = reinterpret_cast<float4*>(g_x);  break;
        case 1:  dst = reinterpret_cast<float4*>(g_wq); break;
        case 2:  dst = reinterpret_cast<float4*>(g_wk); break;
        default: dst = reinterpret_cast<float4*>(g_wv); break;
    }
    int i = blockIdx.x * 256 + threadIdx.x;
    float4 v = src[i];
    dst[i] = make_float4(roundtf(v.x), roundtf(v.y), roundtf(v.z), roundtf(v.w));
}

// Q/K/V = x @ W^T (all inputs pre-rounded; outputs rounded at store)
// grid (HH/BN, (BQ*TT)/BM, 3)
__global__ void __launch_bounds__(256) qkv_kernel() {
    const float* W;
    float* out;
    switch (blockIdx.z) {
        case 0: W = g_wq; out = g_q; break;
        case 1: W = g_wk; out = g_k; break;
        default: W = g_wv; out = g_v; break;
    }
    gemm_nt<false, true>(g_x, W, out, EE, EE, HH, EE,
                         blockIdx.y * BM, blockIdx.x * BN, 1.0f);
}

// Vt[b][h][s] = V[b][s][h] ; grid (HH/32, TT/32, BQ), block (32, 8)
__global__ void __launch_bounds__(256) transpose_kernel() {
    __shared__ float tile[32][33];
    const int b = blockIdx.z;
    const float* src = g_v + (size_t)b * TT * HH;
    float* dst = g_vt + (size_t)b * HH * TT;
    const int h0 = blockIdx.x * 32, s0 = blockIdx.y * 32;
    const int tx = threadIdx.x, ty = threadIdx.y;
#pragma unroll
    for (int i = 0; i < 4; i++)
        tile[ty + 8 * i][tx] = src[(size_t)(s0 + ty + 8 * i) * HH + h0 + tx];
    __syncthreads();
#pragma unroll
    for (int i = 0; i < 4; i++)
        dst[(size_t)(h0 + ty + 8 * i) * TT + s0 + tx] = tile[tx][ty + 8 * i];
}

// S = (Q K^T) * E^-0.5, causal; grid (TT/BN, TT/BM, BQ)
__global__ void __launch_bounds__(256) score_kernel() {
    int b = blockIdx.z;
    int m0 = blockIdx.y * BM, n0 = blockIdx.x * BN;
    if (n0 > m0) return;  // tile entirely above the diagonal -> never read
    const float* Q = g_q + (size_t)b * TT * HH;
    const float* Kp = g_k + (size_t)b * TT * HH;
    float* S = g_s + (size_t)b * TT * TT;
    gemm_nt<true, false>(Q, Kp, S, HH, HH, TT, HH, m0, n0, 0.03125f);  // 1024^-0.5
}

// Row-wise causal softmax in place on g_s; stores tf32-rounded P.
// Zero-fills only up to the 128-rounded row boundary (all pv ever reads).
// grid (BQ*TT)
__global__ void __launch_bounds__(256) softmax_kernel() {
    const int row = blockIdx.x;
    const int b = row >> 11;
    const int t = row & (TT - 1);
    float* S = g_s + (size_t)b * TT * TT + (size_t)t * TT;
    const int tid = threadIdx.x;
    const int lane = tid & 31, warp = tid >> 5;
    const int limit = (t & ~127) + 128;  // pv reads cols [0, limit)
    __shared__ float red[8];

    float v[8];
    float mx = -INFINITY;
#pragma unroll
    for (int i = 0; i < 8; i++) {
        int j = tid + i * 256;
        float s = (j <= t) ? S[j] : -INFINITY;
        v[i] = s;
        mx = fmaxf(mx, s);
    }
#pragma unroll
    for (int o = 16; o; o >>= 1) mx = fmaxf(mx, __shfl_xor_sync(0xffffffffu, mx, o));
    if (lane == 0) red[warp] = mx;
    __syncthreads();
    float bm = red[0];
#pragma unroll
    for (int w = 1; w < 8; w++) bm = fmaxf(bm, red[w]);
    __syncthreads();

    float sum = 0.f;
#pragma unroll
    for (int i = 0; i < 8; i++) {
        int j = tid + i * 256;
        float e = (j <= t) ? expf(v[i] - bm) : 0.f;
        v[i] = e;
        sum += e;
    }
#pragma unroll
    for (int o = 16; o; o >>= 1) sum += __shfl_xor_sync(0xffffffffu, sum, o);
    if (lane == 0) red[warp] = sum;
    __syncthreads();
    float tot = 0.f;
#pragma unroll
    for (int w = 0; w < 8; w++) tot += red[w];
    float inv = 1.f / tot;
#pragma unroll
    for (int i = 0; i < 8; i++) {
        int j = tid + i * 256;
        if (j < limit) S[j] = roundtf(v[i] * inv);
    }
}

// O = P Vt^T ; grid (HH/BN, TT/BM, BQ). P cols >= m0+128 in this row block
// are never nonzero, so truncate K at m0+BM. Conflict-free NT path.
__global__ void __launch_bounds__(256) pv_kernel(float* __restrict__ out) {
    int b = blockIdx.z;
    int m0 = blockIdx.y * BM, n0 = blockIdx.x * BN;
    const float* P = g_s + (size_t)b * TT * TT;
    const float* Vt = g_vt + (size_t)b * HH * TT;
    float* C = out + (size_t)b * TT * HH;
    gemm_nt<false, false>(P, Vt, C, TT, TT, HH, m0 + BM, m0, n0, 1.0f);
}

// ---------------------------------------------------------------------------
extern "C" void kernel_launch(void* const* d_in, const int* in_sizes, int n_in,
                              void* d_out, int out_size) {
    const float* x  = (const float*)d_in[0];
    const float* Wk = (const float*)d_in[1];
    const float* Wq = (const float*)d_in[2];
    const float* Wv = (const float*)d_in[3];
    float* out = (float*)d_out;

    dim3 blk(256);
    const int X4 = (BQ * TT * EE) / 4;   // float4 count for x
    const int W4 = (HH * EE) / 4;

    round_kernel<<<X4 / 256, blk>>>((const float4*)x,  0);
    round_kernel<<<W4 / 256, blk>>>((const float4*)Wq, 1);
    round_kernel<<<W4 / 256, blk>>>((const float4*)Wk, 2);
    round_kernel<<<W4 / 256, blk>>>((const float4*)Wv, 3);

    qkv_kernel<<<dim3(HH / BN, (BQ * TT) / BM, 3), blk>>>();
    transpose_kernel<<<dim3(HH / 32, TT / 32, BQ), dim3(32, 8)>>>();
    score_kernel<<<dim3(TT / BN, TT / BM, BQ), blk>>>();
    softmax_kernel<<<dim3(BQ * TT), blk>>>();
    pv_kernel<<<dim3(HH / BN, TT / BM, BQ), blk>>>(out);
}

// round 12
// speedup vs baseline: 1.3678x; 1.1613x over previous
#include <cuda_runtime.h>
#include <math.h>

// Problem dims
#define BQ 8
#define TT 2048
#define EE 1024
#define HH 1024

// GEMM tile config: CTA 128x128, K staged in 32-wide chunks, 3-stage cp.async
#define BM 128
#define BN 128
#define BKT 32
#define LDAS 36                        // 32 + 4 pad -> conflict-free LDS
#define STG_WORDS (BM * LDAS)          // 4608 words = 18432 B per operand stage
#define STAGES 3
#define SMEM_GEMM (STAGES * 2 * STG_WORDS * 4)  // 110592 B

// Scratch (allocation-free rule: __device__ globals; device-side access ONLY —
// taking these symbols' addresses from host code was the R7 silent-zero bug)
__device__ float g_x [(long long)BQ * TT * EE];   // tf32-rounded x
__device__ float g_wq[(long long)HH * EE];        // tf32-rounded weights
__device__ float g_wk[(long long)HH * EE];
__device__ float g_wv[(long long)HH * EE];
__device__ float g_q [(long long)BQ * TT * HH];   // rounded at store
__device__ float g_k [(long long)BQ * TT * HH];
__device__ float g_v [(long long)BQ * TT * HH];
__device__ float g_vt[(long long)BQ * HH * TT];   // V transposed [b][h][s]
__device__ float g_s [(long long)BQ * TT * TT];   // scores / probs

__device__ __forceinline__ unsigned f2tf(float x) {
    unsigned r;
    asm("cvt.rna.tf32.f32 %0, %1;" : "=r"(r) : "f"(x));
    return r;
}
__device__ __forceinline__ float roundtf(float x) { return __uint_as_float(f2tf(x)); }

__device__ __forceinline__ void mma_tf32(float* c,
                                         unsigned a0, unsigned a1, unsigned a2, unsigned a3,
                                         unsigned b0, unsigned b1) {
    asm volatile(
        "mma.sync.aligned.m16n8k8.row.col.f32.tf32.tf32.f32 "
        "{%0,%1,%2,%3}, {%4,%5,%6,%7}, {%8,%9}, {%0,%1,%2,%3};"
        : "+f"(c[0]), "+f"(c[1]), "+f"(c[2]), "+f"(c[3])
        : "r"(a0), "r"(a1), "r"(a2), "r"(a3), "r"(b0), "r"(b1));
}

__device__ __forceinline__ unsigned smem_u32(const void* p) {
    return (unsigned)__cvta_generic_to_shared(p);
}
__device__ __forceinline__ void cp_async16(unsigned dst, const void* src) {
    asm volatile("cp.async.cg.shared.global [%0], [%1], 16;" :: "r"(dst), "l"(src));
}
__device__ __forceinline__ void cp_commit() { asm volatile("cp.async.commit_group;"); }
__device__ __forceinline__ void cp_wait1()  { asm volatile("cp.async.wait_group 1;"); }

// ---------------------------------------------------------------------------
// C[M,N] = scale * A[M,K] * B[N,K]^T  (A,B row-major, K contiguous for both).
// Inputs PRE-ROUNDED to tf32. 256 threads, 8 warps (4m x 2n), warp tile
// 32x64, m16n8k8 tf32 mma. 3-stage cp.async ring, wait_group 1, ONE barrier
// per BKT=32 k-chunk (4 mma slices between barriers).
// CAUSAL: store only where global col <= global row.
// ROUND:  store outputs rounded to tf32.
// ---------------------------------------------------------------------------
template <bool CAUSAL, bool ROUND>
__device__ __forceinline__ void gemm_nt(const float* __restrict__ A,
                                        const float* __restrict__ B,
                                        float* __restrict__ C,
                                        int lda, int ldb, int ldc,
                                        int K, int m0, int n0, float scale) {
    extern __shared__ unsigned sm[];

    const int tid = threadIdx.x;
    const int warp = tid >> 5, lane = tid & 31;
    const int wm = warp >> 1;  // 0..3
    const int wn = warp & 1;   // 0..1

    float acc[2][8][4];
#pragma unroll
    for (int i = 0; i < 2; i++)
#pragma unroll
        for (int j = 0; j < 8; j++)
#pragma unroll
            for (int r = 0; r < 4; r++) acc[i][j][r] = 0.f;

    // Staging: 16B chunks. Per stage each operand is 128 rows x 32 words =
    // 1024 chunks; 256 threads x 4 chunks. row = chunk>>3, word = (chunk&7)*4.
    auto issue = [&](int s, int ktw) {
        unsigned* as = sm + s * 2 * STG_WORDS;
        unsigned* bs = as + STG_WORDS;
#pragma unroll
        for (int p = 0; p < 4; p++) {
            int chunk = tid + 256 * p;
            int row = chunk >> 3;
            int cw = (chunk & 7) * 4;
            cp_async16(smem_u32(&as[row * LDAS + cw]),
                       A + (size_t)(m0 + row) * lda + ktw + cw);
            cp_async16(smem_u32(&bs[row * LDAS + cw]),
                       B + (size_t)(n0 + row) * ldb + ktw + cw);
        }
        cp_commit();
    };

    const int nk = K / BKT;   // >= 4 for all call sites
    issue(0, 0);
    issue(1, BKT);

    for (int kt = 0; kt < nk; kt++) {
        cp_wait1();           // stage kt resident (kt+1 may still be in flight)
        __syncthreads();
        // Stage (kt+2)%3 was last read in iteration kt-1, which every warp
        // finished before this barrier; issue strictly after it.
        if (kt + 2 < nk) issue((kt + 2) % STAGES, (kt + 2) * BKT);

        const unsigned* as = sm + (kt % STAGES) * 2 * STG_WORDS;
        const unsigned* bs = as + STG_WORDS;

#pragma unroll
        for (int ks = 0; ks < BKT; ks += 8) {
            unsigned a[2][4], b[8][2];
#pragma unroll
            for (int i = 0; i < 2; i++) {
                int r = wm * 32 + i * 16 + (lane >> 2);
                int c = ks + (lane & 3);
                a[i][0] = as[r * LDAS + c];
                a[i][1] = as[(r + 8) * LDAS + c];
                a[i][2] = as[r * LDAS + c + 4];
                a[i][3] = as[(r + 8) * LDAS + c + 4];
            }
#pragma unroll
            for (int j = 0; j < 8; j++) {
                int n = wn * 64 + j * 8 + (lane >> 2);
                int c = ks + (lane & 3);
                b[j][0] = bs[n * LDAS + c];
                b[j][1] = bs[n * LDAS + c + 4];
            }
#pragma unroll
            for (int i = 0; i < 2; i++)
#pragma unroll
                for (int j = 0; j < 8; j++)
                    mma_tf32(acc[i][j], a[i][0], a[i][1], a[i][2], a[i][3],
                             b[j][0], b[j][1]);
        }
    }

#pragma unroll
    for (int i = 0; i < 2; i++) {
        int rbase = m0 + wm * 32 + i * 16 + (lane >> 2);
#pragma unroll
        for (int j = 0; j < 8; j++) {
            int cn = n0 + wn * 64 + j * 8 + (lane & 3) * 2;
#pragma unroll
            for (int h = 0; h < 2; h++) {
                int r = rbase + h * 8;
                float v0 = acc[i][j][2 * h + 0] * scale;
                float v1 = acc[i][j][2 * h + 1] * scale;
                if (ROUND) { v0 = roundtf(v0); v1 = roundtf(v1); }
                if (CAUSAL) {
                    if (cn <= r)     C[(size_t)r * ldc + cn]     = v0;
                    if (cn + 1 <= r) C[(size_t)r * ldc + cn + 1] = v1;
                } else {
                    *reinterpret_cast<float2*>(C + (size_t)r * ldc + cn) =
                        make_float2(v0, v1);
                }
            }
        }
    }
}

// ---------------------------------------------------------------------------
// Kernels
// ---------------------------------------------------------------------------

// tf32 pre-round; dst selected DEVICE-SIDE.
__global__ void __launch_bounds__(256) round_kernel(const float4* __restrict__ src,
                                                    int which) {
    float4* dst;
    switch (which) {
        case 0:  dst = reinterpret_cast<float4*>(g_x);  break;
        case 1:  dst = reinterpret_cast<float4*>(g_wq); break;
        case 2:  dst = reinterpret_cast<float4*>(g_wk); break;
        default: dst = reinterpret_cast<float4*>(g_wv); break;
    }
    int i = blockIdx.x * 256 + threadIdx.x;
    float4 v = src[i];
    dst[i] = make_float4(roundtf(v.x), roundtf(v.y), roundtf(v.z), roundtf(v.w));
}

// Q/K/V = x @ W^T ; grid (HH/BN, (BQ*TT)/BM, 3)
__global__ void __launch_bounds__(256) qkv_kernel() {
    const float* W;
    float* out;
    switch (blockIdx.z) {
        case 0: W = g_wq; out = g_q; break;
        case 1: W = g_wk; out = g_k; break;
        default: W = g_wv; out = g_v; break;
    }
    gemm_nt<false, true>(g_x, W, out, EE, EE, HH, EE,
                         blockIdx.y * BM, blockIdx.x * BN, 1.0f);
}

// Vt[b][h][s] = V[b][s][h] ; grid (HH/32, TT/32, BQ), block (32, 8)
__global__ void __launch_bounds__(256) transpose_kernel() {
    __shared__ float tile[32][33];
    const int b = blockIdx.z;
    const float* src = g_v + (size_t)b * TT * HH;
    float* dst = g_vt + (size_t)b * HH * TT;
    const int h0 = blockIdx.x * 32, s0 = blockIdx.y * 32;
    const int tx = threadIdx.x, ty = threadIdx.y;
#pragma unroll
    for (int i = 0; i < 4; i++)
        tile[ty + 8 * i][tx] = src[(size_t)(s0 + ty + 8 * i) * HH + h0 + tx];
    __syncthreads();
#pragma unroll
    for (int i = 0; i < 4; i++)
        dst[(size_t)(h0 + ty + 8 * i) * TT + s0 + tx] = tile[tx][ty + 8 * i];
}

// S = (Q K^T) * E^-0.5, causal; grid (TT/BN, TT/BM, BQ)
__global__ void __launch_bounds__(256) score_kernel() {
    int b = blockIdx.z;
    int m0 = blockIdx.y * BM, n0 = blockIdx.x * BN;
    if (n0 > m0) return;  // tile entirely above the diagonal -> never read
    const float* Q = g_q + (size_t)b * TT * HH;
    const float* Kp = g_k + (size_t)b * TT * HH;
    float* S = g_s + (size_t)b * TT * TT;
    gemm_nt<true, false>(Q, Kp, S, HH, HH, TT, HH, m0, n0, 0.03125f);  // 1024^-0.5
}

// Row-wise causal softmax in place on g_s; stores tf32-rounded P.
// Zero-fills only up to the 128-rounded boundary pv reads. grid (BQ*TT)
__global__ void __launch_bounds__(256) softmax_kernel() {
    const int row = blockIdx.x;
    const int b = row >> 11;
    const int t = row & (TT - 1);
    float* S = g_s + (size_t)b * TT * TT + (size_t)t * TT;
    const int tid = threadIdx.x;
    const int lane = tid & 31, warp = tid >> 5;
    const int limit = (t & ~127) + 128;
    __shared__ float red[8];

    float v[8];
    float mx = -INFINITY;
#pragma unroll
    for (int i = 0; i < 8; i++) {
        int j = tid + i * 256;
        float s = (j <= t) ? S[j] : -INFINITY;
        v[i] = s;
        mx = fmaxf(mx, s);
    }
#pragma unroll
    for (int o = 16; o; o >>= 1) mx = fmaxf(mx, __shfl_xor_sync(0xffffffffu, mx, o));
    if (lane == 0) red[warp] = mx;
    __syncthreads();
    float bm = red[0];
#pragma unroll
    for (int w = 1; w < 8; w++) bm = fmaxf(bm, red[w]);
    __syncthreads();

    float sum = 0.f;
#pragma unroll
    for (int i = 0; i < 8; i++) {
        int j = tid + i * 256;
        float e = (j <= t) ? expf(v[i] - bm) : 0.f;
        v[i] = e;
        sum += e;
    }
#pragma unroll
    for (int o = 16; o; o >>= 1) sum += __shfl_xor_sync(0xffffffffu, sum, o);
    if (lane == 0) red[warp] = sum;
    __syncthreads();
    float tot = 0.f;
#pragma unroll
    for (int w = 0; w < 8; w++) tot += red[w];
    float inv = 1.f / tot;
#pragma unroll
    for (int i = 0; i < 8; i++) {
        int j = tid + i * 256;
        if (j < limit) S[j] = roundtf(v[i] * inv);
    }
}

// O = P Vt^T ; grid (HH/BN, TT/BM, BQ). K truncated at m0+128 (P zero beyond).
__global__ void __launch_bounds__(256) pv_kernel(float* __restrict__ out) {
    int b = blockIdx.z;
    int m0 = blockIdx.y * BM, n0 = blockIdx.x * BN;
    const float* P = g_s + (size_t)b * TT * TT;
    const float* Vt = g_vt + (size_t)b * HH * TT;
    float* C = out + (size_t)b * TT * HH;
    gemm_nt<false, false>(P, Vt, C, TT, TT, HH, m0 + BM, m0, n0, 1.0f);
}

// ---------------------------------------------------------------------------
extern "C" void kernel_launch(void* const* d_in, const int* in_sizes, int n_in,
                              void* d_out, int out_size) {
    const float* x  = (const float*)d_in[0];
    const float* Wk = (const float*)d_in[1];
    const float* Wq = (const float*)d_in[2];
    const float* Wv = (const float*)d_in[3];
    float* out = (float*)d_out;

    static int smem_set = 0;
    if (!smem_set) {
        cudaFuncSetAttribute(qkv_kernel,   cudaFuncAttributeMaxDynamicSharedMemorySize, SMEM_GEMM);
        cudaFuncSetAttribute(score_kernel, cudaFuncAttributeMaxDynamicSharedMemorySize, SMEM_GEMM);
        cudaFuncSetAttribute(pv_kernel,    cudaFuncAttributeMaxDynamicSharedMemorySize, SMEM_GEMM);
        smem_set = 1;
    }

    dim3 blk(256);
    const int X4 = (BQ * TT * EE) / 4;
    const int W4 = (HH * EE) / 4;

    round_kernel<<<X4 / 256, blk>>>((const float4*)x,  0);
    round_kernel<<<W4 / 256, blk>>>((const float4*)Wq, 1);
    round_kernel<<<W4 / 256, blk>>>((const float4*)Wk, 2);
    round_kernel<<<W4 / 256, blk>>>((const float4*)Wv, 3);

    qkv_kernel<<<dim3(HH / BN, (BQ * TT) / BM, 3), blk, SMEM_GEMM>>>();
    transpose_kernel<<<dim3(HH / 32, TT / 32, BQ), dim3(32, 8)>>>();
    score_kernel<<<dim3(TT / BN, TT / BM, BQ), blk, SMEM_GEMM>>>();
    softmax_kernel<<<dim3(BQ * TT), blk>>>();
    pv_kernel<<<dim3(HH / BN, TT / BM, BQ), blk, SMEM_GEMM>>>(out);
}